// round 13
// baseline (speedup 1.0000x reference)
#include <cuda_runtime.h>
#include <cuda_fp16.h>
#include <cuda_fp8.h>
#include <mma.h>
#include <cstddef>
#include <cstdint>

using namespace nvcuda;

#define NN 100000
#define NE 3200000
#define NCHUNK ((NN + 1023) / 1024)   // 98

// ---------------- scratch (module-load allocated, no runtime alloc) ----------
__device__ __align__(16) __half g_h[(size_t)NN * 128];    // GEMM out L3
__device__ __align__(16) uint8_t g_h8[(size_t)NN * 128];  // fp8 GEMM out
__device__ __align__(16) __half g_act[(size_t)NN * 128];  // GEMM input
__device__ __align__(16) __half g_hd[(size_t)NN * 64];    // Hfinal
__device__ float g_dinv[NN];
__device__ float g_dinv2[NN];
__device__ int g_cnt[NN];
__device__ int g_rowPtr[NN + 1];
__device__ int g_cur[NN];
__device__ __align__(16) unsigned g_ePack[NE];  // (fp16 norm bits)<<17 | src
__device__ int g_chunkSum[NCHUNK];
__device__ int g_chunkOff[NCHUNK + 1];
__device__ int g_is64;

// ---------------- fork/join stream (host-side, created at load time) ---------
struct ForkCtx {
    cudaStream_t s1;
    cudaEvent_t evFork, evJoin;
    ForkCtx() {
        cudaStreamCreateWithFlags(&s1, cudaStreamNonBlocking);
        cudaEventCreateWithFlags(&evFork, cudaEventDisableTiming);
        cudaEventCreateWithFlags(&evJoin, cudaEventDisableTiming);
    }
};
static ForkCtx g_fork;

// ---------------- init: zero counts + edge dtype probe -----------------------
__global__ void k_init(const int* __restrict__ w, int* __restrict__ cnt) {
    int i = blockIdx.x * blockDim.x + threadIdx.x;
    if (i < NN) cnt[i] = 0;
    if (i == 0) {
        int is64 = 1;
        for (int k = 0; k < 2048; k += 2) {
            if (w[k + 1] != 0) { is64 = 0; break; }
        }
        g_is64 = is64;
    }
}

__global__ void k_count(const int* __restrict__ w, int* __restrict__ cnt) {
    const int is64 = g_is64;
    long long i = (long long)blockIdx.x * blockDim.x + threadIdx.x;
    long long stride = (long long)gridDim.x * blockDim.x;
    if (is64) {
        for (; i < NE; i += stride)
            atomicAdd(&cnt[w[2 * (long long)NE + 2 * i]], 1);
    } else {
        for (; i < NE; i += stride)
            atomicAdd(&cnt[w[NE + i]], 1);
    }
}

// ---------------- parallel 3-phase prefix scan -------------------------------
__global__ void __launch_bounds__(1024)
k_chunk_sum(const int* __restrict__ cnt, int* __restrict__ chunkSum) {
    __shared__ int sred[32];
    const int tid = threadIdx.x;
    const int idx = blockIdx.x * 1024 + tid;
    int v = (idx < NN) ? cnt[idx] : 0;
    for (int o = 16; o > 0; o >>= 1) v += __shfl_down_sync(0xffffffffu, v, o);
    if ((tid & 31) == 0) sred[tid >> 5] = v;
    __syncthreads();
    if (tid < 32) {
        int x = sred[tid];
        for (int o = 16; o > 0; o >>= 1) x += __shfl_down_sync(0xffffffffu, x, o);
        if (tid == 0) chunkSum[blockIdx.x] = x;
    }
}

__global__ void __launch_bounds__(128)
k_scan_part(const int* __restrict__ chunkSum, int* __restrict__ chunkOff) {
    __shared__ int s[NCHUNK];
    const int tid = threadIdx.x;
    for (int i = tid; i < NCHUNK; i += 128) s[i] = chunkSum[i];
    __syncthreads();
    if (tid == 0) {
        int acc = 0;
        for (int i = 0; i < NCHUNK; i++) { int v = s[i]; s[i] = acc; acc += v; }
        chunkOff[NCHUNK] = acc;
    }
    __syncthreads();
    for (int i = tid; i < NCHUNK; i += 128) chunkOff[i] = s[i];
}

__global__ void __launch_bounds__(1024)
k_scan_final(const int* __restrict__ cnt, const int* __restrict__ chunkOff,
             int* __restrict__ rowPtr, int* __restrict__ cur,
             float* __restrict__ dinv, float* __restrict__ dinv2) {
    __shared__ int swarp[32];
    const int tid = threadIdx.x;
    const int idx = blockIdx.x * 1024 + tid;
    int v = (idx < NN) ? cnt[idx] : 0;

    int incl = v;
    for (int o = 1; o < 32; o <<= 1) {
        int t = __shfl_up_sync(0xffffffffu, incl, o);
        if ((tid & 31) >= o) incl += t;
    }
    if ((tid & 31) == 31) swarp[tid >> 5] = incl;
    __syncthreads();
    if (tid < 32) {
        int x = swarp[tid];
        for (int o = 1; o < 32; o <<= 1) {
            int t = __shfl_up_sync(0xffffffffu, x, o);
            if (tid >= o) x += t;
        }
        swarp[tid] = x;
    }
    __syncthreads();
    int warpBase = (tid >= 32) ? swarp[(tid >> 5) - 1] : 0;
    int inclTotal = incl + warpBase;

    if (idx < NN) {
        int start = chunkOff[blockIdx.x] + inclTotal - v;
        rowPtr[idx] = start;
        cur[idx] = start;
        float dv = rsqrtf((float)(v + 1));
        dinv[idx] = dv;
        dinv2[idx] = dv * dv;
    }
    if (blockIdx.x == gridDim.x - 1 && tid == 0)
        rowPtr[NN] = chunkOff[NCHUNK];
}

// fill CSR slots: pack = (fp16(norm) bits)<<17 | src
__global__ void k_fill(const int* __restrict__ w, const float* __restrict__ dinv,
                       int* __restrict__ cur, unsigned* __restrict__ ePack) {
    const int is64 = g_is64;
    long long i = (long long)blockIdx.x * blockDim.x + threadIdx.x;
    long long stride = (long long)gridDim.x * blockDim.x;
    for (; i < NE; i += stride) {
        int s, d;
        if (is64) { s = w[2 * i]; d = w[2 * (long long)NE + 2 * i]; }
        else      { s = w[i];     d = w[NE + i]; }
        int pos = atomicAdd(&cur[d], 1);
        unsigned nb = __half_as_ushort(__float2half_rn(dinv[s] * dinv[d]));
        ePack[pos] = (nb << 17) | (unsigned)s;
    }
}

// ---------------- x -> fp16 convert ------------------------------------------
__global__ void k_cvt(const float* __restrict__ x, __half* __restrict__ o) {
    long long i = (long long)blockIdx.x * blockDim.x + threadIdx.x;
    long long stride = (long long)gridDim.x * blockDim.x;
    const long long n4 = (long long)NN * 128 / 4;
    const float4* x4 = reinterpret_cast<const float4*>(x);
    for (; i < n4; i += stride) {
        float4 v = x4[i];
        __half2 p0 = __floats2half2_rn(v.x, v.y);
        __half2 p1 = __floats2half2_rn(v.z, v.w);
        uint2 raw;
        raw.x = *reinterpret_cast<unsigned*>(&p0);
        raw.y = *reinterpret_cast<unsigned*>(&p1);
        *reinterpret_cast<uint2*>(o + 4 * i) = raw;
    }
}

// ---------------- WMMA GEMM: out = in @ W  (fp16), fp8 e4m3 output -----------
__global__ void __launch_bounds__(256)
k_gemm_wmma8(const __half* __restrict__ in, const float* __restrict__ W,
             uint8_t* __restrict__ out8) {
    extern __shared__ __half smg[];
    __half* sW = smg;                         // 128*128
    __half* sStage = smg + 128 * 128;         // 8 * 16 * 128
    const int tid = threadIdx.x;
    for (int i = tid; i < 128 * 128; i += 256) sW[i] = __float2half(W[i]);
    __syncthreads();

    constexpr int TILES = NN / 16;
    const int warpId = tid >> 5;
    const int lane = tid & 31;
    __half* stage = sStage + warpId * 16 * 128;
    const int warpsTotal = (gridDim.x * 256) >> 5;

    for (int tile = blockIdx.x * 8 + warpId; tile < TILES; tile += warpsTotal) {
        const int row0 = tile * 16;
        wmma::fragment<wmma::accumulator, 16, 16, 16, __half> acc[8];
#pragma unroll
        for (int c = 0; c < 8; c++)
            wmma::fill_fragment(acc[c], __float2half(0.0f));

#pragma unroll
        for (int k = 0; k < 8; k++) {
            wmma::fragment<wmma::matrix_a, 16, 16, 16, __half, wmma::row_major> a;
            wmma::load_matrix_sync(a, in + (size_t)row0 * 128 + k * 16, 128);
#pragma unroll
            for (int c = 0; c < 8; c++) {
                wmma::fragment<wmma::matrix_b, 16, 16, 16, __half, wmma::row_major> b;
                wmma::load_matrix_sync(b, sW + k * 16 * 128 + c * 16, 128);
                wmma::mma_sync(acc[c], a, b, acc[c]);
            }
        }
#pragma unroll
        for (int c = 0; c < 8; c++)
            wmma::store_matrix_sync(stage + c * 16, acc[c], 128,
                                    wmma::mem_row_major);
        __syncwarp();

        {
            const int r = lane >> 1;
            const int hOff = (lane & 1) * 64;
            const __half2* src = (const __half2*)(stage + r * 128 + hOff);
            uint8_t* dst = out8 + (size_t)(row0 + r) * 128 + hOff;
#pragma unroll
            for (int g = 0; g < 4; g++) {
                unsigned short f[8];
#pragma unroll
                for (int p = 0; p < 8; p++) {
                    __half2 v = src[g * 8 + p];
                    __half2_raw vr = *reinterpret_cast<__half2_raw*>(&v);
                    f[p] = __nv_cvt_halfraw2_to_fp8x2(vr, __NV_SATFINITE, __NV_E4M3);
                }
                uint4 o;
                o.x = (unsigned)f[0] | ((unsigned)f[1] << 16);
                o.y = (unsigned)f[2] | ((unsigned)f[3] << 16);
                o.z = (unsigned)f[4] | ((unsigned)f[5] << 16);
                o.w = (unsigned)f[6] | ((unsigned)f[7] << 16);
                *reinterpret_cast<uint4*>(dst + g * 16) = o;
            }
        }
        __syncwarp();
    }
}

// ---------------- WMMA GEMM: fp16 out (layer 3) ------------------------------
template <int DIN, int DOUT>
__global__ void __launch_bounds__(256)
k_gemm_wmma(const __half* __restrict__ in, const float* __restrict__ W,
            __half* __restrict__ out) {
    extern __shared__ __half sW[];
    const int tid = threadIdx.x;
    for (int i = tid; i < DIN * DOUT; i += 256) sW[i] = __float2half(W[i]);
    __syncthreads();

    constexpr int TILES = NN / 16;
    const int warpId = tid >> 5;
    const int warpsTotal = (gridDim.x * 256) >> 5;

    for (int tile = blockIdx.x * 8 + warpId; tile < TILES; tile += warpsTotal) {
        const int row0 = tile * 16;
        wmma::fragment<wmma::accumulator, 16, 16, 16, __half> acc[DOUT / 16];
#pragma unroll
        for (int c = 0; c < DOUT / 16; c++)
            wmma::fill_fragment(acc[c], __float2half(0.0f));

#pragma unroll
        for (int k = 0; k < DIN / 16; k++) {
            wmma::fragment<wmma::matrix_a, 16, 16, 16, __half, wmma::row_major> a;
            wmma::load_matrix_sync(a, in + (size_t)row0 * DIN + k * 16, DIN);
#pragma unroll
            for (int c = 0; c < DOUT / 16; c++) {
                wmma::fragment<wmma::matrix_b, 16, 16, 16, __half, wmma::row_major> b;
                wmma::load_matrix_sync(b, sW + k * 16 * DOUT + c * 16, DOUT);
                wmma::mma_sync(acc[c], a, b, acc[c]);
            }
        }
#pragma unroll
        for (int c = 0; c < DOUT / 16; c++)
            wmma::store_matrix_sync(out + (size_t)row0 * DOUT + c * 16, acc[c],
                                    DOUT, wmma::mem_row_major);
    }
}

// ---------------- edge decode helpers ----------------------------------------
__device__ __forceinline__ int edge_src(unsigned v) { return (int)(v & 0x1FFFFu); }
__device__ __forceinline__ __half2 edge_norm_h2(unsigned v) {
    unsigned hb = v >> 17;
    unsigned pair = hb | (hb << 16);
    return *reinterpret_cast<__half2*>(&pair);
}
__device__ __forceinline__ float edge_norm_f(unsigned v) {
    unsigned short hb = (unsigned short)(v >> 17);
    return __half2float(__ushort_as_half(hb));
}

// ---------------- CSR gather, fp8 source (128), half2 accum, 8-deep ----------
__global__ void __launch_bounds__(256)
k_gather8(const int* __restrict__ rowPtr, const unsigned* __restrict__ ePack,
          const uint8_t* __restrict__ h8, const float* __restrict__ dinv2,
          const float* __restrict__ bias, __half* __restrict__ outH) {
    const int lane = threadIdx.x & 31;
    const int warpId = (blockIdx.x * blockDim.x + threadIdx.x) >> 5;
    const int nWarps = (gridDim.x * blockDim.x) >> 5;

    float bl[4];
#pragma unroll
    for (int i = 0; i < 4; i++) bl[i] = bias[lane * 4 + i];

    for (int node = warpId; node < NN; node += nWarps) {
        const int beg = rowPtr[node];
        const int end = rowPtr[node + 1];

        __half2 acc0, acc1, acc2, acc3;
        {
            const float d2 = dinv2[node];
            const __half2 d2h = __float2half2_rn(d2);
            unsigned raw = *reinterpret_cast<const unsigned*>(
                h8 + (size_t)node * 128 + lane * 4);
            __half2_raw r0 = __nv_cvt_fp8x2_to_halfraw2(
                (unsigned short)(raw & 0xffff), __NV_E4M3);
            __half2_raw r1 = __nv_cvt_fp8x2_to_halfraw2(
                (unsigned short)(raw >> 16), __NV_E4M3);
            acc0 = __hmul2(*reinterpret_cast<__half2*>(&r0), d2h);
            acc1 = __hmul2(*reinterpret_cast<__half2*>(&r1), d2h);
            acc2 = __floats2half2_rn(0.0f, 0.0f);
            acc3 = acc2;
        }

        for (int base = beg; base < end; base += 32) {
            const int cnt = min(32, end - base);
            unsigned e = (lane < cnt) ? ePack[base + lane] : 0u;
            int j = 0;
            for (; j + 7 < cnt; j += 8) {
                unsigned v[8]; unsigned raw[8];
#pragma unroll
                for (int q = 0; q < 8; q++)
                    v[q] = __shfl_sync(0xffffffffu, e, j + q);
#pragma unroll
                for (int q = 0; q < 8; q++)
                    raw[q] = *reinterpret_cast<const unsigned*>(
                        h8 + (size_t)edge_src(v[q]) * 128 + lane * 4);
#pragma unroll
                for (int q = 0; q < 8; q++) {
                    __half2 nm = edge_norm_h2(v[q]);
                    __half2_raw r0 = __nv_cvt_fp8x2_to_halfraw2(
                        (unsigned short)(raw[q] & 0xffff), __NV_E4M3);
                    __half2_raw r1 = __nv_cvt_fp8x2_to_halfraw2(
                        (unsigned short)(raw[q] >> 16), __NV_E4M3);
                    if (q & 1) {
                        acc2 = __hfma2(*reinterpret_cast<__half2*>(&r0), nm, acc2);
                        acc3 = __hfma2(*reinterpret_cast<__half2*>(&r1), nm, acc3);
                    } else {
                        acc0 = __hfma2(*reinterpret_cast<__half2*>(&r0), nm, acc0);
                        acc1 = __hfma2(*reinterpret_cast<__half2*>(&r1), nm, acc1);
                    }
                }
            }
            for (; j < cnt; j++) {
                unsigned v = __shfl_sync(0xffffffffu, e, j);
                unsigned raw = *reinterpret_cast<const unsigned*>(
                    h8 + (size_t)edge_src(v) * 128 + lane * 4);
                __half2 nm = edge_norm_h2(v);
                __half2_raw r0 = __nv_cvt_fp8x2_to_halfraw2(
                    (unsigned short)(raw & 0xffff), __NV_E4M3);
                __half2_raw r1 = __nv_cvt_fp8x2_to_halfraw2(
                    (unsigned short)(raw >> 16), __NV_E4M3);
                acc0 = __hfma2(*reinterpret_cast<__half2*>(&r0), nm, acc0);
                acc1 = __hfma2(*reinterpret_cast<__half2*>(&r1), nm, acc1);
            }
        }
        acc0 = __hadd2(acc0, acc2);
        acc1 = __hadd2(acc1, acc3);

        float a0 = fmaxf(__low2float(acc0)  + bl[0], 0.0f);
        float a1 = fmaxf(__high2float(acc0) + bl[1], 0.0f);
        float a2 = fmaxf(__low2float(acc1)  + bl[2], 0.0f);
        float a3 = fmaxf(__high2float(acc1) + bl[3], 0.0f);
        __half2 p0 = __floats2half2_rn(a0, a1);
        __half2 p1 = __floats2half2_rn(a2, a3);
        uint2 raw;
        raw.x = *reinterpret_cast<unsigned*>(&p0);
        raw.y = *reinterpret_cast<unsigned*>(&p1);
        *reinterpret_cast<uint2*>(outH + (size_t)node * 128 + lane * 4) = raw;
    }
}

// ---------------- CSR gather, fp16 src (64) -> fp16 (+b3), 8-deep ------------
__global__ void __launch_bounds__(256)
k_gather64h(const int* __restrict__ rowPtr, const unsigned* __restrict__ ePack,
            const __half* __restrict__ h, const float* __restrict__ dinv2,
            const float* __restrict__ b3, __half* __restrict__ outH) {
    const int lane = threadIdx.x & 31;
    const int warpId = (blockIdx.x * blockDim.x + threadIdx.x) >> 5;
    const int nWarps = (gridDim.x * blockDim.x) >> 5;

    const float b0 = b3[lane * 2];
    const float b1v = b3[lane * 2 + 1];

    for (int node = warpId; node < NN; node += nWarps) {
        const int beg = rowPtr[node];
        const int end = rowPtr[node + 1];

        float acc0, acc1, acc2 = 0.0f, acc3 = 0.0f;
        {
            const float d2 = dinv2[node];
            unsigned raw = *reinterpret_cast<const unsigned*>(
                h + (size_t)node * 64 + lane * 2);
            __half2 a = *reinterpret_cast<__half2*>(&raw);
            acc0 = __low2float(a) * d2;  acc1 = __high2float(a) * d2;
        }

        for (int base = beg; base < end; base += 32) {
            const int cnt = min(32, end - base);
            unsigned e = (lane < cnt) ? ePack[base + lane] : 0u;
            int j = 0;
            for (; j + 7 < cnt; j += 8) {
                unsigned v[8]; unsigned raw[8];
#pragma unroll
                for (int q = 0; q < 8; q++)
                    v[q] = __shfl_sync(0xffffffffu, e, j + q);
#pragma unroll
                for (int q = 0; q < 8; q++)
                    raw[q] = *reinterpret_cast<const unsigned*>(
                        h + (size_t)edge_src(v[q]) * 64 + lane * 2);
#pragma unroll
                for (int q = 0; q < 8; q++) {
                    float nm = edge_norm_f(v[q]);
                    __half2 a = *reinterpret_cast<__half2*>(&raw[q]);
                    if (q & 1) {
                        acc2 = fmaf(__low2float(a),  nm, acc2);
                        acc3 = fmaf(__high2float(a), nm, acc3);
                    } else {
                        acc0 = fmaf(__low2float(a),  nm, acc0);
                        acc1 = fmaf(__high2float(a), nm, acc1);
                    }
                }
            }
            for (; j < cnt; j++) {
                unsigned v = __shfl_sync(0xffffffffu, e, j);
                unsigned raw = *reinterpret_cast<const unsigned*>(
                    h + (size_t)edge_src(v) * 64 + lane * 2);
                float nm = edge_norm_f(v);
                __half2 a = *reinterpret_cast<__half2*>(&raw);
                acc0 = fmaf(__low2float(a),  nm, acc0);
                acc1 = fmaf(__high2float(a), nm, acc1);
            }
        }
        acc0 += acc2;  acc1 += acc3;

        __half2 p = __floats2half2_rn(acc0 + b0, acc1 + b1v);
        *reinterpret_cast<unsigned*>(outH + (size_t)node * 64 + lane * 2) =
            *reinterpret_cast<unsigned*>(&p);
    }
}

// ---------------- fused heads: 6 GEMMs + softmax in one kernel ---------------
constexpr int H_WA1 = 0;               // 64*128
constexpr int H_WC1 = 8192;            // 64*128
constexpr int H_WA2 = 16384;           // 128*64
constexpr int H_WC2 = 24576;           // 128*64
constexpr int H_W3A = 32768;           // 64*16 (Wa3 zero-padded)
constexpr int H_W3C = 33792;           // 64*16 (Wc3 in col 0)
constexpr int H_BA1 = 34816;           // 128
constexpr int H_BC1 = 34944;           // 128
constexpr int H_BA2 = 35072;           // 64
constexpr int H_BC2 = 35136;           // 64
constexpr int H_F32 = 35200;           // 12 floats = 24 halves
constexpr int H_STG = 35264;
constexpr int HPW   = 3584;
constexpr int H_TOT = H_STG + 8 * HPW; // 63936 halves = 127872 B

__global__ void __launch_bounds__(256)
k_heads_fused(const __half* __restrict__ HF,
              const float* __restrict__ Wa1, const float* __restrict__ ba1,
              const float* __restrict__ Wa2, const float* __restrict__ ba2,
              const float* __restrict__ Wa3, const float* __restrict__ ba3,
              const float* __restrict__ Wc1, const float* __restrict__ bc1,
              const float* __restrict__ Wc2, const float* __restrict__ bc2,
              const float* __restrict__ Wc3, const float* __restrict__ bc3,
              float* __restrict__ out) {
    extern __shared__ __half sm[];
    const int tid = threadIdx.x;
    for (int i = tid; i < 8192; i += 256) {
        sm[H_WA1 + i] = __float2half(Wa1[i]);
        sm[H_WC1 + i] = __float2half(Wc1[i]);
        sm[H_WA2 + i] = __float2half(Wa2[i]);
        sm[H_WC2 + i] = __float2half(Wc2[i]);
    }
    for (int i = tid; i < 1024; i += 256) {
        int k = i >> 4, c = i & 15;
        sm[H_W3A + i] = (c < 8) ? __float2half(Wa3[k * 8 + c]) : __float2half(0.0f);
        sm[H_W3C + i] = (c == 0) ? __float2half(Wc3[k]) : __float2half(0.0f);
    }
    if (tid < 128) {
        sm[H_BA1 + tid] = __float2half(ba1[tid]);
        sm[H_BC1 + tid] = __float2half(bc1[tid]);
    }
    if (tid < 64) {
        sm[H_BA2 + tid] = __float2half(ba2[tid]);
        sm[H_BC2 + tid] = __float2half(bc2[tid]);
    }
    float* sF = (float*)(sm + H_F32);
    if (tid < 8) sF[tid] = ba3[tid];
    if (tid == 8) sF[8] = bc3[0];
    __syncthreads();

    constexpr int TILES = NN / 16;
    const int warpId = tid >> 5;
    const int lane = tid & 31;
    __half* stageA = sm + H_STG + warpId * HPW;
    __half* stageB = stageA + 2048;
    float*  stageC = (float*)(stageB + 1024);
    const int warpsTotal = (gridDim.x * 256) >> 5;
    const __half2 zero2 = __floats2half2_rn(0.0f, 0.0f);

    for (int tile = blockIdx.x * 8 + warpId; tile < TILES; tile += warpsTotal) {
        const int row0 = tile * 16;

        wmma::fragment<wmma::matrix_a, 16, 16, 16, __half, wmma::row_major> af[4];
#pragma unroll
        for (int k = 0; k < 4; k++)
            wmma::load_matrix_sync(af[k], HF + (size_t)row0 * 64 + k * 16, 64);

        float lg[8];
        float val = 0.0f;

#pragma unroll
        for (int path = 0; path < 2; path++) {
            const __half* W1p = sm + (path == 0 ? H_WA1 : H_WC1);
            const __half* W2p = sm + (path == 0 ? H_WA2 : H_WC2);
            const __half* W3p = sm + (path == 0 ? H_W3A : H_W3C);
            const __half* B1p = sm + (path == 0 ? H_BA1 : H_BC1);
            const __half* B2p = sm + (path == 0 ? H_BA2 : H_BC2);

            {
                wmma::fragment<wmma::accumulator, 16, 16, 16, __half> acc[8];
#pragma unroll
                for (int c = 0; c < 8; c++)
                    wmma::fill_fragment(acc[c], __float2half(0.0f));
#pragma unroll
                for (int k = 0; k < 4; k++) {
#pragma unroll
                    for (int c = 0; c < 8; c++) {
                        wmma::fragment<wmma::matrix_b, 16, 16, 16, __half,
                                       wmma::row_major> b;
                        wmma::load_matrix_sync(b, W1p + k * 16 * 128 + c * 16, 128);
                        wmma::mma_sync(acc[c], af[k], b, acc[c]);
                    }
                }
#pragma unroll
                for (int c = 0; c < 8; c++)
                    wmma::store_matrix_sync(stageA + c * 16, acc[c], 128,
                                            wmma::mem_row_major);
            }
            __syncwarp();
            {
                const int r = lane >> 1;
                const int off = (lane & 1) * 64;
                __half2* p = (__half2*)(stageA + r * 128 + off);
                const __half2* b2 = (const __half2*)(B1p + off);
#pragma unroll
                for (int i = 0; i < 32; i++)
                    p[i] = __hmax2(__hadd2(p[i], b2[i]), zero2);
            }
            __syncwarp();

            {
                wmma::fragment<wmma::accumulator, 16, 16, 16, __half> acc[4];
#pragma unroll
                for (int c = 0; c < 4; c++)
                    wmma::fill_fragment(acc[c], __float2half(0.0f));
#pragma unroll
                for (int k = 0; k < 8; k++) {
                    wmma::fragment<wmma::matrix_a, 16, 16, 16, __half,
                                   wmma::row_major> a;
                    wmma::load_matrix_sync(a, stageA + k * 16, 128);
#pragma unroll
                    for (int c = 0; c < 4; c++) {
                        wmma::fragment<wmma::matrix_b, 16, 16, 16, __half,
                                       wmma::row_major> b;
                        wmma::load_matrix_sync(b, W2p + k * 16 * 64 + c * 16, 64);
                        wmma::mma_sync(acc[c], a, b, acc[c]);
                    }
                }
#pragma unroll
                for (int c = 0; c < 4; c++)
                    wmma::store_matrix_sync(stageB + c * 16, acc[c], 64,
                                            wmma::mem_row_major);
            }
            __syncwarp();
            {
                const int r = lane >> 1;
                const int off = (lane & 1) * 32;
                __half2* p = (__half2*)(stageB + r * 64 + off);
                const __half2* b2 = (const __half2*)(B2p + off);
#pragma unroll
                for (int i = 0; i < 16; i++)
                    p[i] = __hmax2(__hadd2(p[i], b2[i]), zero2);
            }
            __syncwarp();

            {
                wmma::fragment<wmma::accumulator, 16, 16, 16, float> accf;
                wmma::fill_fragment(accf, 0.0f);
#pragma unroll
                for (int k = 0; k < 4; k++) {
                    wmma::fragment<wmma::matrix_a, 16, 16, 16, __half,
                                   wmma::row_major> a;
                    wmma::load_matrix_sync(a, stageB + k * 16, 64);
                    wmma::fragment<wmma::matrix_b, 16, 16, 16, __half,
                                   wmma::row_major> b;
                    wmma::load_matrix_sync(b, W3p + k * 16 * 16, 16);
                    wmma::mma_sync(accf, a, b, accf);
                }
                wmma::store_matrix_sync(stageC, accf, 16, wmma::mem_row_major);
            }
            __syncwarp();

            if (path == 0) {
                if (lane < 16) {
#pragma unroll
                    for (int a = 0; a < 8; a++)
                        lg[a] = stageC[lane * 16 + a] + sF[a];
                }
            } else {
                if (lane < 16)
                    val = stageC[lane * 16] + sF[8];
            }
            __syncwarp();
        }

        if (lane < 16) {
            float mx = -1e30f;
#pragma unroll
            for (int a = 0; a < 8; a++) mx = fmaxf(mx, lg[a]);
            float e[8], ssum = 0.0f;
#pragma unroll
            for (int a = 0; a < 8; a++) { e[a] = expf(lg[a] - mx); ssum += e[a]; }
            float inv = 1.0f / ssum;
            size_t o = (size_t)(row0 + lane) * 9;
#pragma unroll
            for (int a = 0; a < 8; a++) out[o + a] = e[a] * inv;
            out[o + 8] = val;
        }
        __syncwarp();
    }
}

// ---------------- launch -----------------------------------------------------
extern "C" void kernel_launch(void* const* d_in, const int* in_sizes, int n_in,
                              void* d_out, int out_size) {
    const float* x   = (const float*)d_in[0];
    const int*   eiw = (const int*)d_in[1];
    const float* W1 = (const float*)d_in[2];  const float* b1 = (const float*)d_in[3];
    const float* W2 = (const float*)d_in[4];  const float* b2 = (const float*)d_in[5];
    const float* W3 = (const float*)d_in[6];  const float* b3 = (const float*)d_in[7];
    const float* Wa1 = (const float*)d_in[8];  const float* ba1 = (const float*)d_in[9];
    const float* Wa2 = (const float*)d_in[10]; const float* ba2 = (const float*)d_in[11];
    const float* Wa3 = (const float*)d_in[12]; const float* ba3 = (const float*)d_in[13];
    const float* Wc1 = (const float*)d_in[14]; const float* bc1 = (const float*)d_in[15];
    const float* Wc2 = (const float*)d_in[16]; const float* bc2 = (const float*)d_in[17];
    const float* Wc3 = (const float*)d_in[18]; const float* bc3 = (const float*)d_in[19];
    float* out = (float*)d_out;

    void *ph, *ph8, *pact, *phd, *pdinv, *pdinv2, *pcnt, *prow, *pcur, *pep, *pcs, *pco;
    cudaGetSymbolAddress(&ph, g_h);
    cudaGetSymbolAddress(&ph8, g_h8);
    cudaGetSymbolAddress(&pact, g_act);
    cudaGetSymbolAddress(&phd, g_hd);
    cudaGetSymbolAddress(&pdinv, g_dinv);
    cudaGetSymbolAddress(&pdinv2, g_dinv2);
    cudaGetSymbolAddress(&pcnt, g_cnt);
    cudaGetSymbolAddress(&prow, g_rowPtr);
    cudaGetSymbolAddress(&pcur, g_cur);
    cudaGetSymbolAddress(&pep, g_ePack);
    cudaGetSymbolAddress(&pcs, g_chunkSum);
    cudaGetSymbolAddress(&pco, g_chunkOff);
    __half* H = (__half*)ph;  uint8_t* H8 = (uint8_t*)ph8;
    __half* ACT = (__half*)pact;
    __half* HF = (__half*)phd;
    float* dinv = (float*)pdinv;  float* dinv2 = (float*)pdinv2;
    int* cnt = (int*)pcnt;  int* rowPtr = (int*)prow;  int* cur = (int*)pcur;
    unsigned* ePack = (unsigned*)pep;
    int* chunkSum = (int*)pcs;  int* chunkOff = (int*)pco;

    const int SM_G8 = (128 * 128 + 8 * 16 * 128) * 2;   // 65536
    const int SM_W2 = 128 * 64 * 2;                     // 16384
    const int SM_HF = H_TOT * 2;                        // 127872

    cudaFuncSetAttribute(k_gemm_wmma8,
                         cudaFuncAttributeMaxDynamicSharedMemorySize, SM_G8);
    cudaFuncSetAttribute(k_gemm_wmma<128, 64>,
                         cudaFuncAttributeMaxDynamicSharedMemorySize, SM_W2);
    cudaFuncSetAttribute(k_heads_fused,
                         cudaFuncAttributeMaxDynamicSharedMemorySize, SM_HF);

    cudaStream_t s1 = g_fork.s1;

    // ---- fork: stream s1 runs cvt + layer-1 GEMM concurrently with CSR build
    cudaEventRecord(g_fork.evFork, 0);
    cudaStreamWaitEvent(s1, g_fork.evFork, 0);

    // main stream: CSR build
    k_init<<<(NN + 255) / 256, 256>>>(eiw, cnt);
    k_count<<<1184, 256>>>(eiw, cnt);
    k_chunk_sum<<<NCHUNK, 1024>>>(cnt, chunkSum);
    k_scan_part<<<1, 128>>>(chunkSum, chunkOff);
    k_scan_final<<<NCHUNK, 1024>>>(cnt, chunkOff, rowPtr, cur, dinv, dinv2);
    k_fill<<<1184, 256>>>(eiw, dinv, cur, ePack);

    // forked stream: x -> fp16, layer-1 GEMM
    k_cvt<<<1184, 256, 0, s1>>>(x, ACT);
    k_gemm_wmma8<<<391, 256, SM_G8, s1>>>(ACT, W1, H8);

    // join
    cudaEventRecord(g_fork.evJoin, s1);
    cudaStreamWaitEvent(0, g_fork.evJoin, 0);

    // ---- layer 1 gather ----
    k_gather8<<<1184, 256>>>(rowPtr, ePack, H8, dinv2, b1, ACT);

    // ---- layer 2 ----
    k_gemm_wmma8<<<391, 256, SM_G8>>>(ACT, W2, H8);
    k_gather8<<<1184, 256>>>(rowPtr, ePack, H8, dinv2, b2, ACT);

    // ---- layer 3 ----
    k_gemm_wmma<128, 64><<<391, 256, SM_W2>>>(ACT, W3, H);
    k_gather64h<<<1184, 256>>>(rowPtr, ePack, H, dinv2, b3, HF);

    // ---- fused heads + softmax -> out ----
    k_heads_fused<<<296, 256, SM_HF>>>(HF,
                                       Wa1, ba1, Wa2, ba2, Wa3, ba3,
                                       Wc1, bc1, Wc2, bc2, Wc3, bc3, out);
}

// round 14
// speedup vs baseline: 1.0331x; 1.0331x over previous
#include <cuda_runtime.h>
#include <cuda_fp16.h>
#include <cuda_fp8.h>
#include <mma.h>
#include <cstddef>
#include <cstdint>

using namespace nvcuda;

#define NN 100000
#define NE 3200000
#define NCHUNK ((NN + 1023) / 1024)   // 98

// ---------------- scratch (module-load allocated, no runtime alloc) ----------
__device__ __align__(16) __half g_h[(size_t)NN * 128];    // (spare)
__device__ __align__(16) uint8_t g_h8[(size_t)NN * 128];  // fp8 GEMM out
__device__ __align__(16) __half g_act[(size_t)NN * 128];  // GEMM input
__device__ __align__(16) __half g_hd[(size_t)NN * 64];    // Hfinal
__device__ float g_dinv[NN];
__device__ float g_dinv2[NN];
__device__ int g_cnt[NN];
__device__ int g_rowPtr[NN + 1];
__device__ int g_cur[NN];
__device__ __align__(16) unsigned g_ePack[NE];  // (fp16 norm bits)<<17 | src
__device__ int g_chunkSum[NCHUNK];
__device__ int g_chunkOff[NCHUNK + 1];
__device__ int g_is64;

// ---------------- fork/join stream (host-side, created at load time) ---------
struct ForkCtx {
    cudaStream_t s1;
    cudaEvent_t evFork, evJoin;
    ForkCtx() {
        cudaStreamCreateWithFlags(&s1, cudaStreamNonBlocking);
        cudaEventCreateWithFlags(&evFork, cudaEventDisableTiming);
        cudaEventCreateWithFlags(&evJoin, cudaEventDisableTiming);
    }
};
static ForkCtx g_fork;

// ---------------- init: zero counts + edge dtype probe -----------------------
__global__ void k_init(const int* __restrict__ w, int* __restrict__ cnt) {
    int i = blockIdx.x * blockDim.x + threadIdx.x;
    if (i < NN) cnt[i] = 0;
    if (i == 0) {
        int is64 = 1;
        for (int k = 0; k < 2048; k += 2) {
            if (w[k + 1] != 0) { is64 = 0; break; }
        }
        g_is64 = is64;
    }
}

__global__ void k_count(const int* __restrict__ w, int* __restrict__ cnt) {
    const int is64 = g_is64;
    long long i = (long long)blockIdx.x * blockDim.x + threadIdx.x;
    long long stride = (long long)gridDim.x * blockDim.x;
    if (is64) {
        for (; i < NE; i += stride)
            atomicAdd(&cnt[w[2 * (long long)NE + 2 * i]], 1);
    } else {
        for (; i < NE; i += stride)
            atomicAdd(&cnt[w[NE + i]], 1);
    }
}

// ---------------- parallel 3-phase prefix scan -------------------------------
__global__ void __launch_bounds__(1024)
k_chunk_sum(const int* __restrict__ cnt, int* __restrict__ chunkSum) {
    __shared__ int sred[32];
    const int tid = threadIdx.x;
    const int idx = blockIdx.x * 1024 + tid;
    int v = (idx < NN) ? cnt[idx] : 0;
    for (int o = 16; o > 0; o >>= 1) v += __shfl_down_sync(0xffffffffu, v, o);
    if ((tid & 31) == 0) sred[tid >> 5] = v;
    __syncthreads();
    if (tid < 32) {
        int x = sred[tid];
        for (int o = 16; o > 0; o >>= 1) x += __shfl_down_sync(0xffffffffu, x, o);
        if (tid == 0) chunkSum[blockIdx.x] = x;
    }
}

__global__ void __launch_bounds__(128)
k_scan_part(const int* __restrict__ chunkSum, int* __restrict__ chunkOff) {
    __shared__ int s[NCHUNK];
    const int tid = threadIdx.x;
    for (int i = tid; i < NCHUNK; i += 128) s[i] = chunkSum[i];
    __syncthreads();
    if (tid == 0) {
        int acc = 0;
        for (int i = 0; i < NCHUNK; i++) { int v = s[i]; s[i] = acc; acc += v; }
        chunkOff[NCHUNK] = acc;
    }
    __syncthreads();
    for (int i = tid; i < NCHUNK; i += 128) chunkOff[i] = s[i];
}

__global__ void __launch_bounds__(1024)
k_scan_final(const int* __restrict__ cnt, const int* __restrict__ chunkOff,
             int* __restrict__ rowPtr, int* __restrict__ cur,
             float* __restrict__ dinv, float* __restrict__ dinv2) {
    __shared__ int swarp[32];
    const int tid = threadIdx.x;
    const int idx = blockIdx.x * 1024 + tid;
    int v = (idx < NN) ? cnt[idx] : 0;

    int incl = v;
    for (int o = 1; o < 32; o <<= 1) {
        int t = __shfl_up_sync(0xffffffffu, incl, o);
        if ((tid & 31) >= o) incl += t;
    }
    if ((tid & 31) == 31) swarp[tid >> 5] = incl;
    __syncthreads();
    if (tid < 32) {
        int x = swarp[tid];
        for (int o = 1; o < 32; o <<= 1) {
            int t = __shfl_up_sync(0xffffffffu, x, o);
            if (tid >= o) x += t;
        }
        swarp[tid] = x;
    }
    __syncthreads();
    int warpBase = (tid >= 32) ? swarp[(tid >> 5) - 1] : 0;
    int inclTotal = incl + warpBase;

    if (idx < NN) {
        int start = chunkOff[blockIdx.x] + inclTotal - v;
        rowPtr[idx] = start;
        cur[idx] = start;
        float dv = rsqrtf((float)(v + 1));
        dinv[idx] = dv;
        dinv2[idx] = dv * dv;
    }
    if (blockIdx.x == gridDim.x - 1 && tid == 0)
        rowPtr[NN] = chunkOff[NCHUNK];
}

// fill CSR slots: pack = (fp16(norm) bits)<<17 | src
__global__ void k_fill(const int* __restrict__ w, const float* __restrict__ dinv,
                       int* __restrict__ cur, unsigned* __restrict__ ePack) {
    const int is64 = g_is64;
    long long i = (long long)blockIdx.x * blockDim.x + threadIdx.x;
    long long stride = (long long)gridDim.x * blockDim.x;
    for (; i < NE; i += stride) {
        int s, d;
        if (is64) { s = w[2 * i]; d = w[2 * (long long)NE + 2 * i]; }
        else      { s = w[i];     d = w[NE + i]; }
        int pos = atomicAdd(&cur[d], 1);
        unsigned nb = __half_as_ushort(__float2half_rn(dinv[s] * dinv[d]));
        ePack[pos] = (nb << 17) | (unsigned)s;
    }
}

// ---------------- x -> fp16 convert ------------------------------------------
__global__ void k_cvt(const float* __restrict__ x, __half* __restrict__ o) {
    long long i = (long long)blockIdx.x * blockDim.x + threadIdx.x;
    long long stride = (long long)gridDim.x * blockDim.x;
    const long long n4 = (long long)NN * 128 / 4;
    const float4* x4 = reinterpret_cast<const float4*>(x);
    for (; i < n4; i += stride) {
        float4 v = x4[i];
        __half2 p0 = __floats2half2_rn(v.x, v.y);
        __half2 p1 = __floats2half2_rn(v.z, v.w);
        uint2 raw;
        raw.x = *reinterpret_cast<unsigned*>(&p0);
        raw.y = *reinterpret_cast<unsigned*>(&p1);
        *reinterpret_cast<uint2*>(o + 4 * i) = raw;
    }
}

// ---------------- WMMA GEMM templated on DOUT, fp8 e4m3 output ---------------
template <int DOUT>
__global__ void __launch_bounds__(256)
k_gemm_wmma8(const __half* __restrict__ in, const float* __restrict__ W,
             uint8_t* __restrict__ out8) {
    extern __shared__ __half smg[];
    __half* sW = smg;                         // 128*DOUT
    __half* sStage = smg + 128 * DOUT;        // 8 * 16 * DOUT
    const int tid = threadIdx.x;
    for (int i = tid; i < 128 * DOUT; i += 256) sW[i] = __float2half(W[i]);
    __syncthreads();

    constexpr int TILES = NN / 16;
    constexpr int NC = DOUT / 16;
    const int warpId = tid >> 5;
    const int lane = tid & 31;
    __half* stage = sStage + warpId * 16 * DOUT;
    const int warpsTotal = (gridDim.x * 256) >> 5;

    for (int tile = blockIdx.x * 8 + warpId; tile < TILES; tile += warpsTotal) {
        const int row0 = tile * 16;
        wmma::fragment<wmma::accumulator, 16, 16, 16, __half> acc[NC];
#pragma unroll
        for (int c = 0; c < NC; c++)
            wmma::fill_fragment(acc[c], __float2half(0.0f));

#pragma unroll
        for (int k = 0; k < 8; k++) {
            wmma::fragment<wmma::matrix_a, 16, 16, 16, __half, wmma::row_major> a;
            wmma::load_matrix_sync(a, in + (size_t)row0 * 128 + k * 16, 128);
#pragma unroll
            for (int c = 0; c < NC; c++) {
                wmma::fragment<wmma::matrix_b, 16, 16, 16, __half, wmma::row_major> b;
                wmma::load_matrix_sync(b, sW + k * 16 * DOUT + c * 16, DOUT);
                wmma::mma_sync(acc[c], a, b, acc[c]);
            }
        }
#pragma unroll
        for (int c = 0; c < NC; c++)
            wmma::store_matrix_sync(stage + c * 16, acc[c], DOUT,
                                    wmma::mem_row_major);
        __syncwarp();

        // epilogue: lane owns half a row (DOUT/2 halves -> DOUT/2 fp8 bytes)
        {
            const int r = lane >> 1;
            const int hOff = (lane & 1) * (DOUT / 2);
            const __half2* src = (const __half2*)(stage + r * DOUT + hOff);
            uint8_t* dst = out8 + (size_t)(row0 + r) * DOUT + hOff;
#pragma unroll
            for (int g = 0; g < DOUT / 32; g++) {
                unsigned short f[8];
#pragma unroll
                for (int p = 0; p < 8; p++) {
                    __half2 v = src[g * 8 + p];
                    __half2_raw vr = *reinterpret_cast<__half2_raw*>(&v);
                    f[p] = __nv_cvt_halfraw2_to_fp8x2(vr, __NV_SATFINITE, __NV_E4M3);
                }
                uint4 o;
                o.x = (unsigned)f[0] | ((unsigned)f[1] << 16);
                o.y = (unsigned)f[2] | ((unsigned)f[3] << 16);
                o.z = (unsigned)f[4] | ((unsigned)f[5] << 16);
                o.w = (unsigned)f[6] | ((unsigned)f[7] << 16);
                *reinterpret_cast<uint4*>(dst + g * 16) = o;
            }
        }
        __syncwarp();
    }
}

// ---------------- edge decode helpers ----------------------------------------
__device__ __forceinline__ int edge_src(unsigned v) { return (int)(v & 0x1FFFFu); }
__device__ __forceinline__ __half2 edge_norm_h2(unsigned v) {
    unsigned hb = v >> 17;
    unsigned pair = hb | (hb << 16);
    return *reinterpret_cast<__half2*>(&pair);
}
__device__ __forceinline__ float edge_norm_f(unsigned v) {
    unsigned short hb = (unsigned short)(v >> 17);
    return __half2float(__ushort_as_half(hb));
}

// ---------------- CSR gather, fp8 source (128), half2 accum, 8-deep ----------
__global__ void __launch_bounds__(512)
k_gather8(const int* __restrict__ rowPtr, const unsigned* __restrict__ ePack,
          const uint8_t* __restrict__ h8, const float* __restrict__ dinv2,
          const float* __restrict__ bias, __half* __restrict__ outH) {
    const int lane = threadIdx.x & 31;
    const int warpId = (blockIdx.x * blockDim.x + threadIdx.x) >> 5;
    const int nWarps = (gridDim.x * blockDim.x) >> 5;

    float bl[4];
#pragma unroll
    for (int i = 0; i < 4; i++) bl[i] = bias[lane * 4 + i];

    for (int node = warpId; node < NN; node += nWarps) {
        const int beg = rowPtr[node];
        const int end = rowPtr[node + 1];

        __half2 acc0, acc1, acc2, acc3;
        {
            const float d2 = dinv2[node];
            const __half2 d2h = __float2half2_rn(d2);
            unsigned raw = *reinterpret_cast<const unsigned*>(
                h8 + (size_t)node * 128 + lane * 4);
            __half2_raw r0 = __nv_cvt_fp8x2_to_halfraw2(
                (unsigned short)(raw & 0xffff), __NV_E4M3);
            __half2_raw r1 = __nv_cvt_fp8x2_to_halfraw2(
                (unsigned short)(raw >> 16), __NV_E4M3);
            acc0 = __hmul2(*reinterpret_cast<__half2*>(&r0), d2h);
            acc1 = __hmul2(*reinterpret_cast<__half2*>(&r1), d2h);
            acc2 = __floats2half2_rn(0.0f, 0.0f);
            acc3 = acc2;
        }

        for (int base = beg; base < end; base += 32) {
            const int cnt = min(32, end - base);
            unsigned e = (lane < cnt) ? ePack[base + lane] : 0u;
            int j = 0;
            for (; j + 7 < cnt; j += 8) {
                unsigned v[8]; unsigned raw[8];
#pragma unroll
                for (int q = 0; q < 8; q++)
                    v[q] = __shfl_sync(0xffffffffu, e, j + q);
#pragma unroll
                for (int q = 0; q < 8; q++)
                    raw[q] = *reinterpret_cast<const unsigned*>(
                        h8 + (size_t)edge_src(v[q]) * 128 + lane * 4);
#pragma unroll
                for (int q = 0; q < 8; q++) {
                    __half2 nm = edge_norm_h2(v[q]);
                    __half2_raw r0 = __nv_cvt_fp8x2_to_halfraw2(
                        (unsigned short)(raw[q] & 0xffff), __NV_E4M3);
                    __half2_raw r1 = __nv_cvt_fp8x2_to_halfraw2(
                        (unsigned short)(raw[q] >> 16), __NV_E4M3);
                    if (q & 1) {
                        acc2 = __hfma2(*reinterpret_cast<__half2*>(&r0), nm, acc2);
                        acc3 = __hfma2(*reinterpret_cast<__half2*>(&r1), nm, acc3);
                    } else {
                        acc0 = __hfma2(*reinterpret_cast<__half2*>(&r0), nm, acc0);
                        acc1 = __hfma2(*reinterpret_cast<__half2*>(&r1), nm, acc1);
                    }
                }
            }
            for (; j < cnt; j++) {
                unsigned v = __shfl_sync(0xffffffffu, e, j);
                unsigned raw = *reinterpret_cast<const unsigned*>(
                    h8 + (size_t)edge_src(v) * 128 + lane * 4);
                __half2 nm = edge_norm_h2(v);
                __half2_raw r0 = __nv_cvt_fp8x2_to_halfraw2(
                    (unsigned short)(raw & 0xffff), __NV_E4M3);
                __half2_raw r1 = __nv_cvt_fp8x2_to_halfraw2(
                    (unsigned short)(raw >> 16), __NV_E4M3);
                acc0 = __hfma2(*reinterpret_cast<__half2*>(&r0), nm, acc0);
                acc1 = __hfma2(*reinterpret_cast<__half2*>(&r1), nm, acc1);
            }
        }
        acc0 = __hadd2(acc0, acc2);
        acc1 = __hadd2(acc1, acc3);

        float a0 = fmaxf(__low2float(acc0)  + bl[0], 0.0f);
        float a1 = fmaxf(__high2float(acc0) + bl[1], 0.0f);
        float a2 = fmaxf(__low2float(acc1)  + bl[2], 0.0f);
        float a3 = fmaxf(__high2float(acc1) + bl[3], 0.0f);
        __half2 p0 = __floats2half2_rn(a0, a1);
        __half2 p1 = __floats2half2_rn(a2, a3);
        uint2 raw;
        raw.x = *reinterpret_cast<unsigned*>(&p0);
        raw.y = *reinterpret_cast<unsigned*>(&p1);
        *reinterpret_cast<uint2*>(outH + (size_t)node * 128 + lane * 4) = raw;
    }
}

// ---------------- CSR gather, fp8 src (64) -> fp16 (+b3), 8-deep -------------
__global__ void __launch_bounds__(512)
k_gather64_8(const int* __restrict__ rowPtr, const unsigned* __restrict__ ePack,
             const uint8_t* __restrict__ h8, const float* __restrict__ dinv2,
             const float* __restrict__ b3, __half* __restrict__ outH) {
    const int lane = threadIdx.x & 31;
    const int warpId = (blockIdx.x * blockDim.x + threadIdx.x) >> 5;
    const int nWarps = (gridDim.x * blockDim.x) >> 5;

    const float b0 = b3[lane * 2];
    const float b1v = b3[lane * 2 + 1];

    for (int node = warpId; node < NN; node += nWarps) {
        const int beg = rowPtr[node];
        const int end = rowPtr[node + 1];

        float acc0, acc1, acc2 = 0.0f, acc3 = 0.0f;
        {
            const float d2 = dinv2[node];
            unsigned short raw = *reinterpret_cast<const unsigned short*>(
                h8 + (size_t)node * 64 + lane * 2);
            __half2_raw hr = __nv_cvt_fp8x2_to_halfraw2(raw, __NV_E4M3);
            __half2 a = *reinterpret_cast<__half2*>(&hr);
            acc0 = __low2float(a) * d2;  acc1 = __high2float(a) * d2;
        }

        for (int base = beg; base < end; base += 32) {
            const int cnt = min(32, end - base);
            unsigned e = (lane < cnt) ? ePack[base + lane] : 0u;
            int j = 0;
            for (; j + 7 < cnt; j += 8) {
                unsigned v[8]; unsigned short raw[8];
#pragma unroll
                for (int q = 0; q < 8; q++)
                    v[q] = __shfl_sync(0xffffffffu, e, j + q);
#pragma unroll
                for (int q = 0; q < 8; q++)
                    raw[q] = *reinterpret_cast<const unsigned short*>(
                        h8 + (size_t)edge_src(v[q]) * 64 + lane * 2);
#pragma unroll
                for (int q = 0; q < 8; q++) {
                    float nm = edge_norm_f(v[q]);
                    __half2_raw hr = __nv_cvt_fp8x2_to_halfraw2(raw[q], __NV_E4M3);
                    __half2 a = *reinterpret_cast<__half2*>(&hr);
                    if (q & 1) {
                        acc2 = fmaf(__low2float(a),  nm, acc2);
                        acc3 = fmaf(__high2float(a), nm, acc3);
                    } else {
                        acc0 = fmaf(__low2float(a),  nm, acc0);
                        acc1 = fmaf(__high2float(a), nm, acc1);
                    }
                }
            }
            for (; j < cnt; j++) {
                unsigned v = __shfl_sync(0xffffffffu, e, j);
                unsigned short raw = *reinterpret_cast<const unsigned short*>(
                    h8 + (size_t)edge_src(v) * 64 + lane * 2);
                float nm = edge_norm_f(v);
                __half2_raw hr = __nv_cvt_fp8x2_to_halfraw2(raw, __NV_E4M3);
                __half2 a = *reinterpret_cast<__half2*>(&hr);
                acc0 = fmaf(__low2float(a),  nm, acc0);
                acc1 = fmaf(__high2float(a), nm, acc1);
            }
        }
        acc0 += acc2;  acc1 += acc3;

        __half2 p = __floats2half2_rn(acc0 + b0, acc1 + b1v);
        *reinterpret_cast<unsigned*>(outH + (size_t)node * 64 + lane * 2) =
            *reinterpret_cast<unsigned*>(&p);
    }
}

// ---------------- fused heads: 6 GEMMs + softmax in one kernel ---------------
constexpr int H_WA1 = 0;               // 64*128
constexpr int H_WC1 = 8192;            // 64*128
constexpr int H_WA2 = 16384;           // 128*64
constexpr int H_WC2 = 24576;           // 128*64
constexpr int H_W3A = 32768;           // 64*16 (Wa3 zero-padded)
constexpr int H_W3C = 33792;           // 64*16 (Wc3 in col 0)
constexpr int H_BA1 = 34816;           // 128
constexpr int H_BC1 = 34944;           // 128
constexpr int H_BA2 = 35072;           // 64
constexpr int H_BC2 = 35136;           // 64
constexpr int H_F32 = 35200;           // 12 floats = 24 halves
constexpr int H_STG = 35264;
constexpr int HPW   = 3584;
constexpr int H_TOT = H_STG + 8 * HPW; // 63936 halves = 127872 B

__global__ void __launch_bounds__(256)
k_heads_fused(const __half* __restrict__ HF,
              const float* __restrict__ Wa1, const float* __restrict__ ba1,
              const float* __restrict__ Wa2, const float* __restrict__ ba2,
              const float* __restrict__ Wa3, const float* __restrict__ ba3,
              const float* __restrict__ Wc1, const float* __restrict__ bc1,
              const float* __restrict__ Wc2, const float* __restrict__ bc2,
              const float* __restrict__ Wc3, const float* __restrict__ bc3,
              float* __restrict__ out) {
    extern __shared__ __half sm[];
    const int tid = threadIdx.x;
    for (int i = tid; i < 8192; i += 256) {
        sm[H_WA1 + i] = __float2half(Wa1[i]);
        sm[H_WC1 + i] = __float2half(Wc1[i]);
        sm[H_WA2 + i] = __float2half(Wa2[i]);
        sm[H_WC2 + i] = __float2half(Wc2[i]);
    }
    for (int i = tid; i < 1024; i += 256) {
        int k = i >> 4, c = i & 15;
        sm[H_W3A + i] = (c < 8) ? __float2half(Wa3[k * 8 + c]) : __float2half(0.0f);
        sm[H_W3C + i] = (c == 0) ? __float2half(Wc3[k]) : __float2half(0.0f);
    }
    if (tid < 128) {
        sm[H_BA1 + tid] = __float2half(ba1[tid]);
        sm[H_BC1 + tid] = __float2half(bc1[tid]);
    }
    if (tid < 64) {
        sm[H_BA2 + tid] = __float2half(ba2[tid]);
        sm[H_BC2 + tid] = __float2half(bc2[tid]);
    }
    float* sF = (float*)(sm + H_F32);
    if (tid < 8) sF[tid] = ba3[tid];
    if (tid == 8) sF[8] = bc3[0];
    __syncthreads();

    constexpr int TILES = NN / 16;
    const int warpId = tid >> 5;
    const int lane = tid & 31;
    __half* stageA = sm + H_STG + warpId * HPW;
    __half* stageB = stageA + 2048;
    float*  stageC = (float*)(stageB + 1024);
    const int warpsTotal = (gridDim.x * 256) >> 5;
    const __half2 zero2 = __floats2half2_rn(0.0f, 0.0f);

    for (int tile = blockIdx.x * 8 + warpId; tile < TILES; tile += warpsTotal) {
        const int row0 = tile * 16;

        wmma::fragment<wmma::matrix_a, 16, 16, 16, __half, wmma::row_major> af[4];
#pragma unroll
        for (int k = 0; k < 4; k++)
            wmma::load_matrix_sync(af[k], HF + (size_t)row0 * 64 + k * 16, 64);

        float lg[8];
        float val = 0.0f;

#pragma unroll
        for (int path = 0; path < 2; path++) {
            const __half* W1p = sm + (path == 0 ? H_WA1 : H_WC1);
            const __half* W2p = sm + (path == 0 ? H_WA2 : H_WC2);
            const __half* W3p = sm + (path == 0 ? H_W3A : H_W3C);
            const __half* B1p = sm + (path == 0 ? H_BA1 : H_BC1);
            const __half* B2p = sm + (path == 0 ? H_BA2 : H_BC2);

            {
                wmma::fragment<wmma::accumulator, 16, 16, 16, __half> acc[8];
#pragma unroll
                for (int c = 0; c < 8; c++)
                    wmma::fill_fragment(acc[c], __float2half(0.0f));
#pragma unroll
                for (int k = 0; k < 4; k++) {
#pragma unroll
                    for (int c = 0; c < 8; c++) {
                        wmma::fragment<wmma::matrix_b, 16, 16, 16, __half,
                                       wmma::row_major> b;
                        wmma::load_matrix_sync(b, W1p + k * 16 * 128 + c * 16, 128);
                        wmma::mma_sync(acc[c], af[k], b, acc[c]);
                    }
                }
#pragma unroll
                for (int c = 0; c < 8; c++)
                    wmma::store_matrix_sync(stageA + c * 16, acc[c], 128,
                                            wmma::mem_row_major);
            }
            __syncwarp();
            {
                const int r = lane >> 1;
                const int off = (lane & 1) * 64;
                __half2* p = (__half2*)(stageA + r * 128 + off);
                const __half2* b2 = (const __half2*)(B1p + off);
#pragma unroll
                for (int i = 0; i < 32; i++)
                    p[i] = __hmax2(__hadd2(p[i], b2[i]), zero2);
            }
            __syncwarp();

            {
                wmma::fragment<wmma::accumulator, 16, 16, 16, __half> acc[4];
#pragma unroll
                for (int c = 0; c < 4; c++)
                    wmma::fill_fragment(acc[c], __float2half(0.0f));
#pragma unroll
                for (int k = 0; k < 8; k++) {
                    wmma::fragment<wmma::matrix_a, 16, 16, 16, __half,
                                   wmma::row_major> a;
                    wmma::load_matrix_sync(a, stageA + k * 16, 128);
#pragma unroll
                    for (int c = 0; c < 4; c++) {
                        wmma::fragment<wmma::matrix_b, 16, 16, 16, __half,
                                       wmma::row_major> b;
                        wmma::load_matrix_sync(b, W2p + k * 16 * 64 + c * 16, 64);
                        wmma::mma_sync(acc[c], a, b, acc[c]);
                    }
                }
#pragma unroll
                for (int c = 0; c < 4; c++)
                    wmma::store_matrix_sync(stageB + c * 16, acc[c], 64,
                                            wmma::mem_row_major);
            }
            __syncwarp();
            {
                const int r = lane >> 1;
                const int off = (lane & 1) * 32;
                __half2* p = (__half2*)(stageB + r * 64 + off);
                const __half2* b2 = (const __half2*)(B2p + off);
#pragma unroll
                for (int i = 0; i < 16; i++)
                    p[i] = __hmax2(__hadd2(p[i], b2[i]), zero2);
            }
            __syncwarp();

            {
                wmma::fragment<wmma::accumulator, 16, 16, 16, float> accf;
                wmma::fill_fragment(accf, 0.0f);
#pragma unroll
                for (int k = 0; k < 4; k++) {
                    wmma::fragment<wmma::matrix_a, 16, 16, 16, __half,
                                   wmma::row_major> a;
                    wmma::load_matrix_sync(a, stageB + k * 16, 64);
                    wmma::fragment<wmma::matrix_b, 16, 16, 16, __half,
                                   wmma::row_major> b;
                    wmma::load_matrix_sync(b, W3p + k * 16 * 16, 16);
                    wmma::mma_sync(accf, a, b, accf);
                }
                wmma::store_matrix_sync(stageC, accf, 16, wmma::mem_row_major);
            }
            __syncwarp();

            if (path == 0) {
                if (lane < 16) {
#pragma unroll
                    for (int a = 0; a < 8; a++)
                        lg[a] = stageC[lane * 16 + a] + sF[a];
                }
            } else {
                if (lane < 16)
                    val = stageC[lane * 16] + sF[8];
            }
            __syncwarp();
        }

        if (lane < 16) {
            float mx = -1e30f;
#pragma unroll
            for (int a = 0; a < 8; a++) mx = fmaxf(mx, lg[a]);
            float e[8], ssum = 0.0f;
#pragma unroll
            for (int a = 0; a < 8; a++) { e[a] = expf(lg[a] - mx); ssum += e[a]; }
            float inv = 1.0f / ssum;
            size_t o = (size_t)(row0 + lane) * 9;
#pragma unroll
            for (int a = 0; a < 8; a++) out[o + a] = e[a] * inv;
            out[o + 8] = val;
        }
        __syncwarp();
    }
}

// ---------------- launch -----------------------------------------------------
extern "C" void kernel_launch(void* const* d_in, const int* in_sizes, int n_in,
                              void* d_out, int out_size) {
    const float* x   = (const float*)d_in[0];
    const int*   eiw = (const int*)d_in[1];
    const float* W1 = (const float*)d_in[2];  const float* b1 = (const float*)d_in[3];
    const float* W2 = (const float*)d_in[4];  const float* b2 = (const float*)d_in[5];
    const float* W3 = (const float*)d_in[6];  const float* b3 = (const float*)d_in[7];
    const float* Wa1 = (const float*)d_in[8];  const float* ba1 = (const float*)d_in[9];
    const float* Wa2 = (const float*)d_in[10]; const float* ba2 = (const float*)d_in[11];
    const float* Wa3 = (const float*)d_in[12]; const float* ba3 = (const float*)d_in[13];
    const float* Wc1 = (const float*)d_in[14]; const float* bc1 = (const float*)d_in[15];
    const float* Wc2 = (const float*)d_in[16]; const float* bc2 = (const float*)d_in[17];
    const float* Wc3 = (const float*)d_in[18]; const float* bc3 = (const float*)d_in[19];
    float* out = (float*)d_out;

    void *ph8, *pact, *phd, *pdinv, *pdinv2, *pcnt, *prow, *pcur, *pep, *pcs, *pco;
    cudaGetSymbolAddress(&ph8, g_h8);
    cudaGetSymbolAddress(&pact, g_act);
    cudaGetSymbolAddress(&phd, g_hd);
    cudaGetSymbolAddress(&pdinv, g_dinv);
    cudaGetSymbolAddress(&pdinv2, g_dinv2);
    cudaGetSymbolAddress(&pcnt, g_cnt);
    cudaGetSymbolAddress(&prow, g_rowPtr);
    cudaGetSymbolAddress(&pcur, g_cur);
    cudaGetSymbolAddress(&pep, g_ePack);
    cudaGetSymbolAddress(&pcs, g_chunkSum);
    cudaGetSymbolAddress(&pco, g_chunkOff);
    uint8_t* H8 = (uint8_t*)ph8;
    __half* ACT = (__half*)pact;
    __half* HF = (__half*)phd;
    float* dinv = (float*)pdinv;  float* dinv2 = (float*)pdinv2;
    int* cnt = (int*)pcnt;  int* rowPtr = (int*)prow;  int* cur = (int*)pcur;
    unsigned* ePack = (unsigned*)pep;
    int* chunkSum = (int*)pcs;  int* chunkOff = (int*)pco;

    const int SM_G8A = (128 * 128 + 8 * 16 * 128) * 2;  // 65536
    const int SM_G8B = (128 * 64 + 8 * 16 * 64) * 2;    // 32768
    const int SM_HF = H_TOT * 2;                        // 127872

    cudaFuncSetAttribute(k_gemm_wmma8<128>,
                         cudaFuncAttributeMaxDynamicSharedMemorySize, SM_G8A);
    cudaFuncSetAttribute(k_gemm_wmma8<64>,
                         cudaFuncAttributeMaxDynamicSharedMemorySize, SM_G8B);
    cudaFuncSetAttribute(k_heads_fused,
                         cudaFuncAttributeMaxDynamicSharedMemorySize, SM_HF);

    cudaStream_t s1 = g_fork.s1;

    // ---- fork: stream s1 runs cvt + layer-1 GEMM concurrently with CSR build
    cudaEventRecord(g_fork.evFork, 0);
    cudaStreamWaitEvent(s1, g_fork.evFork, 0);

    // main stream: CSR build
    k_init<<<(NN + 255) / 256, 256>>>(eiw, cnt);
    k_count<<<1184, 256>>>(eiw, cnt);
    k_chunk_sum<<<NCHUNK, 1024>>>(cnt, chunkSum);
    k_scan_part<<<1, 128>>>(chunkSum, chunkOff);
    k_scan_final<<<NCHUNK, 1024>>>(cnt, chunkOff, rowPtr, cur, dinv, dinv2);
    k_fill<<<1184, 256>>>(eiw, dinv, cur, ePack);

    // forked stream: x -> fp16, layer-1 GEMM
    k_cvt<<<1184, 256, 0, s1>>>(x, ACT);
    k_gemm_wmma8<128><<<391, 256, SM_G8A, s1>>>(ACT, W1, H8);

    // join
    cudaEventRecord(g_fork.evJoin, s1);
    cudaStreamWaitEvent(0, g_fork.evJoin, 0);

    // ---- layer 1 gather ----
    k_gather8<<<592, 512>>>(rowPtr, ePack, H8, dinv2, b1, ACT);

    // ---- layer 2 ----
    k_gemm_wmma8<128><<<391, 256, SM_G8A>>>(ACT, W2, H8);
    k_gather8<<<592, 512>>>(rowPtr, ePack, H8, dinv2, b2, ACT);

    // ---- layer 3 (fp8 64-dim) ----
    k_gemm_wmma8<64><<<391, 256, SM_G8B>>>(ACT, W3, H8);
    k_gather64_8<<<592, 512>>>(rowPtr, ePack, H8, dinv2, b3, HF);

    // ---- fused heads + softmax -> out ----
    k_heads_fused<<<296, 256, SM_HF>>>(HF,
                                       Wa1, ba1, Wa2, ba2, Wa3, ba3,
                                       Wc1, bc1, Wc2, bc2, Wc3, bc3, out);
}